// round 1
// baseline (speedup 1.0000x reference)
#include <cuda_runtime.h>
#include <math.h>

#define TOKENS 2048
#define HIDDEN 2048
#define INTER  1408
#define NEXP   8

// ---------------- scratch (device globals; no allocation) ----------------
__device__ int   g_counts[NEXP];
__device__ int   g_pairs[NEXP * TOKENS];          // encoded (t<<1)|slot
__device__ float g_wts[TOKENS * 2];               // combine weight per (t,slot)
__device__ float g_hbuf[(size_t)TOKENS * 2 * INTER];   // gated intermediate, row = (t<<1)|slot
__device__ float g_ybuf[(size_t)TOKENS * 2 * HIDDEN];  // down-proj result per (t,slot)

// ---------------- kernel 0: zero expert counters ----------------
__global__ void zero_counts_kernel() {
    if (threadIdx.x < NEXP) g_counts[threadIdx.x] = 0;
}

// ---------------- kernel 1: router ----------------
// One block (256 threads) per token. logits = x_t @ w_router[H,E], top-2,
// renormalized weights (softmax denominators cancel), scatter to expert lists.
__global__ __launch_bounds__(256) void router_kernel(
    const float* __restrict__ x, const float* __restrict__ wr)
{
    int t = blockIdx.x;
    __shared__ float red[256][NEXP];

    float acc[NEXP];
#pragma unroll
    for (int e = 0; e < NEXP; e++) acc[e] = 0.f;

    const float* xr = x + (size_t)t * HIDDEN;
    for (int h = threadIdx.x; h < HIDDEN; h += 256) {
        float xv = xr[h];
        const float* w = wr + (size_t)h * NEXP;
#pragma unroll
        for (int e = 0; e < NEXP; e++) acc[e] += xv * w[e];
    }
#pragma unroll
    for (int e = 0; e < NEXP; e++) red[threadIdx.x][e] = acc[e];
    __syncthreads();

    for (int s = 128; s > 0; s >>= 1) {
        if (threadIdx.x < s) {
#pragma unroll
            for (int e = 0; e < NEXP; e++)
                red[threadIdx.x][e] += red[threadIdx.x + s][e];
        }
        __syncthreads();
    }

    if (threadIdx.x == 0) {
        float l[NEXP];
#pragma unroll
        for (int e = 0; e < NEXP; e++) l[e] = red[0][e];
        // top-1 (first max on ties, matching lax.top_k tie order)
        int i0 = 0;
#pragma unroll
        for (int e = 1; e < NEXP; e++) if (l[e] > l[i0]) i0 = e;
        // top-2
        int i1 = -1;
#pragma unroll
        for (int e = 0; e < NEXP; e++) {
            if (e == i0) continue;
            if (i1 < 0 || l[e] > l[i1]) i1 = e;
        }
        // renormalized top-2 softmax weights: exp(l0)/(exp(l0)+exp(l1))
        float w0 = 1.f / (1.f + __expf(l[i1] - l[i0]));
        float w1 = 1.f - w0;

        int p0 = atomicAdd(&g_counts[i0], 1);
        g_pairs[i0 * TOKENS + p0] = (t << 1);
        int p1 = atomicAdd(&g_counts[i1], 1);
        g_pairs[i1 * TOKENS + p1] = (t << 1) | 1;
        g_wts[(t << 1)]     = w0;
        g_wts[(t << 1) | 1] = w1;
    }
}

// ---------------- kernel 2: grouped gate+up GEMM + fused SiLU epilogue ----------------
// Per expert e: A = gathered token rows [cnt, H], B = w_gate[e]/w_up[e] [H, I].
// C tile 64x64, K tile 16, 256 threads, 4x4 microtile per thread.
__global__ __launch_bounds__(256) void gateup_kernel(
    const float* __restrict__ x,
    const float* __restrict__ wg,
    const float* __restrict__ wu)
{
    const int e   = blockIdx.z;
    const int cnt = g_counts[e];
    const int m0  = blockIdx.y * 64;
    if (m0 >= cnt) return;
    const int n0  = blockIdx.x * 64;

    __shared__ float As[16][64];   // k-major
    __shared__ float Bg[16][64];
    __shared__ float Bu[16][64];
    __shared__ int   rows[64];

    const int tid = threadIdx.x;
    if (tid < 64) {
        int m = m0 + tid;
        rows[tid] = (m < cnt) ? g_pairs[e * TOKENS + m] : -1;
    }
    __syncthreads();

    const int tx = tid & 15;
    const int ty = tid >> 4;

    float acc_g[4][4], acc_u[4][4];
#pragma unroll
    for (int i = 0; i < 4; i++)
#pragma unroll
        for (int j = 0; j < 4; j++) { acc_g[i][j] = 0.f; acc_u[i][j] = 0.f; }

    const float* wge = wg + (size_t)e * HIDDEN * INTER;
    const float* wue = wu + (size_t)e * HIDDEN * INTER;

    const int arow = tid >> 2;          // 0..63
    const int akk  = (tid & 3) * 4;     // 0,4,8,12
    const int brow = tid >> 4;          // 0..15
    const int bcol = (tid & 15) * 4;    // 0..60

    const int  pa   = rows[arow];
    const float* xrow = (pa >= 0) ? (x + (size_t)(pa >> 1) * HIDDEN) : x;

    for (int k0 = 0; k0 < HIDDEN; k0 += 16) {
        float4 av = (pa >= 0) ? *(const float4*)(xrow + k0 + akk)
                              : make_float4(0.f, 0.f, 0.f, 0.f);
        As[akk + 0][arow] = av.x;
        As[akk + 1][arow] = av.y;
        As[akk + 2][arow] = av.z;
        As[akk + 3][arow] = av.w;

        float4 bgv = *(const float4*)(wge + (size_t)(k0 + brow) * INTER + n0 + bcol);
        float4 buv = *(const float4*)(wue + (size_t)(k0 + brow) * INTER + n0 + bcol);
        *(float4*)&Bg[brow][bcol] = bgv;
        *(float4*)&Bu[brow][bcol] = buv;
        __syncthreads();

#pragma unroll
        for (int k = 0; k < 16; k++) {
            float a[4], bg[4], bu[4];
#pragma unroll
            for (int i = 0; i < 4; i++) a[i]  = As[k][ty * 4 + i];
#pragma unroll
            for (int j = 0; j < 4; j++) { bg[j] = Bg[k][tx * 4 + j]; bu[j] = Bu[k][tx * 4 + j]; }
#pragma unroll
            for (int i = 0; i < 4; i++)
#pragma unroll
                for (int j = 0; j < 4; j++) {
                    acc_g[i][j] += a[i] * bg[j];
                    acc_u[i][j] += a[i] * bu[j];
                }
        }
        __syncthreads();
    }

    // epilogue: h = silu(g) * u * combine_weight, scatter to hbuf[(t,slot)]
#pragma unroll
    for (int i = 0; i < 4; i++) {
        int pr = rows[ty * 4 + i];
        if (pr < 0) continue;
        float w = g_wts[pr];
        float* hout = g_hbuf + (size_t)pr * INTER + n0 + tx * 4;
#pragma unroll
        for (int j = 0; j < 4; j++) {
            float g = acc_g[i][j];
            float u = acc_u[i][j];
            float s = g / (1.f + __expf(-g));
            hout[j] = s * u * w;
        }
    }
}

// ---------------- kernel 3: grouped down GEMM ----------------
// Per expert e: A = gathered hbuf rows [cnt, I], B = w_down[e] [I, H].
__global__ __launch_bounds__(256) void down_kernel(const float* __restrict__ wd)
{
    const int e   = blockIdx.z;
    const int cnt = g_counts[e];
    const int m0  = blockIdx.y * 64;
    if (m0 >= cnt) return;
    const int n0  = blockIdx.x * 64;

    __shared__ float As[16][64];
    __shared__ float Bs[16][64];
    __shared__ int   rows[64];

    const int tid = threadIdx.x;
    if (tid < 64) {
        int m = m0 + tid;
        rows[tid] = (m < cnt) ? g_pairs[e * TOKENS + m] : -1;
    }
    __syncthreads();

    const int tx = tid & 15;
    const int ty = tid >> 4;

    float acc[4][4];
#pragma unroll
    for (int i = 0; i < 4; i++)
#pragma unroll
        for (int j = 0; j < 4; j++) acc[i][j] = 0.f;

    const float* wde = wd + (size_t)e * INTER * HIDDEN;

    const int arow = tid >> 2;
    const int akk  = (tid & 3) * 4;
    const int brow = tid >> 4;
    const int bcol = (tid & 15) * 4;

    const int pa = rows[arow];
    const float* hrow = (pa >= 0) ? (g_hbuf + (size_t)pa * INTER) : g_hbuf;

    for (int k0 = 0; k0 < INTER; k0 += 16) {
        float4 av = (pa >= 0) ? *(const float4*)(hrow + k0 + akk)
                              : make_float4(0.f, 0.f, 0.f, 0.f);
        As[akk + 0][arow] = av.x;
        As[akk + 1][arow] = av.y;
        As[akk + 2][arow] = av.z;
        As[akk + 3][arow] = av.w;

        float4 bv = *(const float4*)(wde + (size_t)(k0 + brow) * HIDDEN + n0 + bcol);
        *(float4*)&Bs[brow][bcol] = bv;
        __syncthreads();

#pragma unroll
        for (int k = 0; k < 16; k++) {
            float a[4], b[4];
#pragma unroll
            for (int i = 0; i < 4; i++) a[i] = As[k][ty * 4 + i];
#pragma unroll
            for (int j = 0; j < 4; j++) b[j] = Bs[k][tx * 4 + j];
#pragma unroll
            for (int i = 0; i < 4; i++)
#pragma unroll
                for (int j = 0; j < 4; j++) acc[i][j] += a[i] * b[j];
        }
        __syncthreads();
    }

#pragma unroll
    for (int i = 0; i < 4; i++) {
        int pr = rows[ty * 4 + i];
        if (pr < 0) continue;
        float* yout = g_ybuf + (size_t)pr * HIDDEN + n0 + tx * 4;
#pragma unroll
        for (int j = 0; j < 4; j++) yout[j] = acc[i][j];
    }
}

// ---------------- kernel 4: combine the two expert slots per token ----------------
__global__ __launch_bounds__(256) void combine_kernel(float* __restrict__ out)
{
    size_t idx = (size_t)blockIdx.x * blockDim.x + threadIdx.x;   // float4 index
    size_t total = (size_t)TOKENS * HIDDEN / 4;
    if (idx >= total) return;
    size_t t = idx / (HIDDEN / 4);
    size_t c = idx % (HIDDEN / 4);
    const float4* y0 = (const float4*)(g_ybuf + (size_t)(t * 2)     * HIDDEN) + c;
    const float4* y1 = (const float4*)(g_ybuf + (size_t)(t * 2 + 1) * HIDDEN) + c;
    float4 a = *y0, b = *y1;
    float4 r = make_float4(a.x + b.x, a.y + b.y, a.z + b.z, a.w + b.w);
    ((float4*)out)[idx] = r;
}

// ---------------- launch ----------------
extern "C" void kernel_launch(void* const* d_in, const int* in_sizes, int n_in,
                              void* d_out, int out_size)
{
    const float* x  = (const float*)d_in[0];  // [T, H]
    const float* wr = (const float*)d_in[1];  // [H, E]
    const float* wg = (const float*)d_in[2];  // [E, H, I]
    const float* wu = (const float*)d_in[3];  // [E, H, I]
    const float* wd = (const float*)d_in[4];  // [E, I, H]
    float* out = (float*)d_out;               // [T, H]

    zero_counts_kernel<<<1, 32>>>();
    router_kernel<<<TOKENS, 256>>>(x, wr);

    dim3 g1(INTER / 64, TOKENS / 64, NEXP);   // 22 x 32 x 8
    gateup_kernel<<<g1, 256>>>(x, wg, wu);

    dim3 g2(HIDDEN / 64, TOKENS / 64, NEXP);  // 32 x 32 x 8
    down_kernel<<<g2, 256>>>(wd);

    size_t total4 = (size_t)TOKENS * HIDDEN / 4;
    combine_kernel<<<(unsigned)((total4 + 255) / 256), 256>>>(out);
}

// round 3
// speedup vs baseline: 1.4492x; 1.4492x over previous
#include <cuda_runtime.h>
#include <cstdint>
#include <math.h>

#define TOKENS 2048
#define HIDDEN 2048
#define INTER  1408
#define NEXP   8
#define KT     32
#define LDA    36   // 32 + 4 pad (floats): conflict-free frag loads

// ---------------- device scratch (no allocation) ----------------
__device__ int   g_counts[NEXP];
__device__ int   g_pairs[NEXP * TOKENS];               // encoded (t<<1)|slot
__device__ float g_wts[TOKENS * 2];                    // combine weight per (t,slot)
__device__ float g_hbuf[(size_t)TOKENS * 2 * INTER];   // gated intermediate
__device__ float g_ybuf[(size_t)TOKENS * 2 * HIDDEN];  // down-proj per (t,slot)

__device__ __forceinline__ uint32_t f2tf32(float f) {
    uint32_t u;
    asm("cvt.rna.tf32.f32 %0, %1;" : "=r"(u) : "f"(f));
    return u;
}

// m16n8k8 tf32 MMA (standard PTX, sm_80+; legacy HMMA path on Blackwell)
__device__ __forceinline__ void mma_tf32(float* c, const uint32_t* a, const uint32_t* b) {
    asm volatile(
        "mma.sync.aligned.m16n8k8.row.col.f32.tf32.tf32.f32 "
        "{%0,%1,%2,%3}, {%4,%5,%6,%7}, {%8,%9}, {%0,%1,%2,%3};"
        : "+f"(c[0]), "+f"(c[1]), "+f"(c[2]), "+f"(c[3])
        : "r"(a[0]), "r"(a[1]), "r"(a[2]), "r"(a[3]), "r"(b[0]), "r"(b[1]));
}

// ---------------- kernel 0: zero counters ----------------
__global__ void zero_counts_kernel() {
    if (threadIdx.x < NEXP) g_counts[threadIdx.x] = 0;
}

// ---------------- kernel 1: router ----------------
__global__ __launch_bounds__(256) void router_kernel(
    const float* __restrict__ x, const float* __restrict__ wr)
{
    int t = blockIdx.x;
    __shared__ float red[256][NEXP];
    float acc[NEXP];
#pragma unroll
    for (int e = 0; e < NEXP; e++) acc[e] = 0.f;
    const float* xr = x + (size_t)t * HIDDEN;
    for (int h = threadIdx.x; h < HIDDEN; h += 256) {
        float xv = xr[h];
        const float* w = wr + (size_t)h * NEXP;
#pragma unroll
        for (int e = 0; e < NEXP; e++) acc[e] += xv * w[e];
    }
#pragma unroll
    for (int e = 0; e < NEXP; e++) red[threadIdx.x][e] = acc[e];
    __syncthreads();
    for (int s = 128; s > 0; s >>= 1) {
        if (threadIdx.x < s) {
#pragma unroll
            for (int e = 0; e < NEXP; e++)
                red[threadIdx.x][e] += red[threadIdx.x + s][e];
        }
        __syncthreads();
    }
    if (threadIdx.x == 0) {
        float l[NEXP];
#pragma unroll
        for (int e = 0; e < NEXP; e++) l[e] = red[0][e];
        int i0 = 0;
#pragma unroll
        for (int e = 1; e < NEXP; e++) if (l[e] > l[i0]) i0 = e;
        int i1 = -1;
#pragma unroll
        for (int e = 0; e < NEXP; e++) {
            if (e == i0) continue;
            if (i1 < 0 || l[e] > l[i1]) i1 = e;
        }
        float w0 = 1.f / (1.f + __expf(l[i1] - l[i0]));
        float w1 = 1.f - w0;
        int p0 = atomicAdd(&g_counts[i0], 1);
        g_pairs[i0 * TOKENS + p0] = (t << 1);
        int p1 = atomicAdd(&g_counts[i1], 1);
        g_pairs[i1 * TOKENS + p1] = (t << 1) | 1;
        g_wts[(t << 1)]     = w0;
        g_wts[(t << 1) | 1] = w1;
    }
}

// ---------------- kernel 2: grouped gate+up GEMM (tf32 mma.sync) ----------------
// Block tile: M=128 gathered rows x 64 output cols (gate+up interleaved as 128
// B-rows at 16-col granularity). Warp tile 64x32 (4x4 m16n8k8).
__global__ __launch_bounds__(256, 2) void gateup_kernel(
    const float* __restrict__ x,
    const float* __restrict__ wg,
    const float* __restrict__ wu)
{
    const int e   = blockIdx.z;
    const int cnt = g_counts[e];
    const int m0  = blockIdx.y * 128;
    if (m0 >= cnt) return;
    const int n0  = blockIdx.x * 64;

    __shared__ uint32_t A_s[128 * LDA];
    __shared__ uint32_t B_s[128 * LDA];
    __shared__ int rows_sh[128];

    const int tid  = threadIdx.x;
    const int wid  = tid >> 5;
    const int lane = tid & 31;
    const int gr   = lane >> 2;   // group id 0..7
    const int tg   = lane & 3;    // thread-in-group 0..3
    const int wm   = (wid & 1) * 64;   // warp m offset
    const int wn   = (wid >> 1) * 32;  // warp B-col offset

    if (tid < 128) {
        int m = m0 + tid;
        rows_sh[tid] = (m < cnt) ? g_pairs[e * TOKENS + m] : -1;
    }

    const float* wge = wg + (size_t)e * HIDDEN * INTER;
    const float* wue = wu + (size_t)e * HIDDEN * INTER;

    float acc[4][4][4];
#pragma unroll
    for (int i = 0; i < 4; i++)
#pragma unroll
        for (int j = 0; j < 4; j++)
#pragma unroll
            for (int c = 0; c < 4; c++) acc[i][j][c] = 0.f;

    __syncthreads();

    for (int k0 = 0; k0 < HIDDEN; k0 += KT) {
        // ---- stage A [128m x 32k], gathered ----
#pragma unroll
        for (int i = 0; i < 4; i++) {
            int q  = tid + 256 * i;          // 0..1023
            int m  = q >> 3;
            int k4 = (q & 7) * 4;
            int pr = rows_sh[m];
            float4 v = make_float4(0.f, 0.f, 0.f, 0.f);
            if (pr >= 0)
                v = *(const float4*)(x + (size_t)(pr >> 1) * HIDDEN + k0 + k4);
            uint4 o = make_uint4(f2tf32(v.x), f2tf32(v.y), f2tf32(v.z), f2tf32(v.w));
            *(uint4*)&A_s[m * LDA + k4] = o;
        }
        // ---- stage B: B_s[r][k] where r interleaves gate/up per 16 cols ----
#pragma unroll
        for (int i = 0; i < 4; i++) {
            int q  = tid + 256 * i;
            int k  = q >> 5;                 // 0..31
            int r0 = (q & 31) * 4;           // 0..124
            int w  = r0 >> 5;
            int half = (r0 >> 4) & 1;
            int nn = n0 + w * 16 + (r0 & 15);
            const float* src = (half ? wue : wge) + (size_t)(k0 + k) * INTER + nn;
            float4 v = *(const float4*)src;
            B_s[(r0 + 0) * LDA + k] = f2tf32(v.x);
            B_s[(r0 + 1) * LDA + k] = f2tf32(v.y);
            B_s[(r0 + 2) * LDA + k] = f2tf32(v.z);
            B_s[(r0 + 3) * LDA + k] = f2tf32(v.w);
        }
        __syncthreads();

#pragma unroll
        for (int ks = 0; ks < 4; ks++) {
            const int k = ks * 8;
            uint32_t a[4][4];
#pragma unroll
            for (int mi = 0; mi < 4; mi++) {
                int r = wm + mi * 16 + gr;
                a[mi][0] = A_s[r * LDA + k + tg];
                a[mi][1] = A_s[(r + 8) * LDA + k + tg];
                a[mi][2] = A_s[r * LDA + k + tg + 4];
                a[mi][3] = A_s[(r + 8) * LDA + k + tg + 4];
            }
            uint32_t b[4][2];
#pragma unroll
            for (int nj = 0; nj < 4; nj++) {
                int r = wn + nj * 8 + gr;
                b[nj][0] = B_s[r * LDA + k + tg];
                b[nj][1] = B_s[r * LDA + k + tg + 4];
            }
#pragma unroll
            for (int mi = 0; mi < 4; mi++)
#pragma unroll
                for (int nj = 0; nj < 4; nj++)
                    mma_tf32(acc[mi][nj], a[mi], b[nj]);
        }
        __syncthreads();
    }

    // ---- epilogue: silu(gate)*up*wt, thread-local pairing ----
    // nfrag 0,1 = gate, nfrag 2,3 = up at the same output cols.
    const int colbase = n0 + (wid >> 1) * 16 + 2 * tg;
#pragma unroll
    for (int mi = 0; mi < 4; mi++) {
#pragma unroll
        for (int half = 0; half < 2; half++) {
            int row = wm + mi * 16 + gr + half * 8;
            int pr  = rows_sh[row];
            if (pr < 0) continue;
            float wt = g_wts[pr];
            float* hrow = g_hbuf + (size_t)pr * INTER;
#pragma unroll
            for (int nj = 0; nj < 2; nj++) {
                float g0 = acc[mi][nj][half * 2 + 0];
                float g1 = acc[mi][nj][half * 2 + 1];
                float u0 = acc[mi][nj + 2][half * 2 + 0];
                float u1 = acc[mi][nj + 2][half * 2 + 1];
                float h0 = (g0 / (1.f + __expf(-g0))) * u0 * wt;
                float h1 = (g1 / (1.f + __expf(-g1))) * u1 * wt;
                *(float2*)&hrow[colbase + nj * 8] = make_float2(h0, h1);
            }
        }
    }
}

// ---------------- kernel 3: grouped down GEMM (tf32 mma.sync) ----------------
// Block tile 128 x 128, K = INTER.
__global__ __launch_bounds__(256, 2) void down_kernel(const float* __restrict__ wd)
{
    const int e   = blockIdx.z;
    const int cnt = g_counts[e];
    const int m0  = blockIdx.y * 128;
    if (m0 >= cnt) return;
    const int n0  = blockIdx.x * 128;

    __shared__ uint32_t A_s[128 * LDA];
    __shared__ uint32_t B_s[128 * LDA];
    __shared__ int rows_sh[128];

    const int tid  = threadIdx.x;
    const int wid  = tid >> 5;
    const int lane = tid & 31;
    const int gr   = lane >> 2;
    const int tg   = lane & 3;
    const int wm   = (wid & 1) * 64;
    const int wn   = (wid >> 1) * 32;

    if (tid < 128) {
        int m = m0 + tid;
        rows_sh[tid] = (m < cnt) ? g_pairs[e * TOKENS + m] : -1;
    }

    const float* wde = wd + (size_t)e * INTER * HIDDEN;

    float acc[4][4][4];
#pragma unroll
    for (int i = 0; i < 4; i++)
#pragma unroll
        for (int j = 0; j < 4; j++)
#pragma unroll
            for (int c = 0; c < 4; c++) acc[i][j][c] = 0.f;

    __syncthreads();

    for (int k0 = 0; k0 < INTER; k0 += KT) {
#pragma unroll
        for (int i = 0; i < 4; i++) {
            int q  = tid + 256 * i;
            int m  = q >> 3;
            int k4 = (q & 7) * 4;
            int pr = rows_sh[m];
            float4 v = make_float4(0.f, 0.f, 0.f, 0.f);
            if (pr >= 0)
                v = *(const float4*)(g_hbuf + (size_t)pr * INTER + k0 + k4);
            uint4 o = make_uint4(f2tf32(v.x), f2tf32(v.y), f2tf32(v.z), f2tf32(v.w));
            *(uint4*)&A_s[m * LDA + k4] = o;
        }
#pragma unroll
        for (int i = 0; i < 4; i++) {
            int q  = tid + 256 * i;
            int k  = q >> 5;
            int r0 = (q & 31) * 4;
            const float* src = wde + (size_t)(k0 + k) * HIDDEN + n0 + r0;
            float4 v = *(const float4*)src;
            B_s[(r0 + 0) * LDA + k] = f2tf32(v.x);
            B_s[(r0 + 1) * LDA + k] = f2tf32(v.y);
            B_s[(r0 + 2) * LDA + k] = f2tf32(v.z);
            B_s[(r0 + 3) * LDA + k] = f2tf32(v.w);
        }
        __syncthreads();

#pragma unroll
        for (int ks = 0; ks < 4; ks++) {
            const int k = ks * 8;
            uint32_t a[4][4];
#pragma unroll
            for (int mi = 0; mi < 4; mi++) {
                int r = wm + mi * 16 + gr;
                a[mi][0] = A_s[r * LDA + k + tg];
                a[mi][1] = A_s[(r + 8) * LDA + k + tg];
                a[mi][2] = A_s[r * LDA + k + tg + 4];
                a[mi][3] = A_s[(r + 8) * LDA + k + tg + 4];
            }
            uint32_t b[4][2];
#pragma unroll
            for (int nj = 0; nj < 4; nj++) {
                int r = wn + nj * 8 + gr;
                b[nj][0] = B_s[r * LDA + k + tg];
                b[nj][1] = B_s[r * LDA + k + tg + 4];
            }
#pragma unroll
            for (int mi = 0; mi < 4; mi++)
#pragma unroll
                for (int nj = 0; nj < 4; nj++)
                    mma_tf32(acc[mi][nj], a[mi], b[nj]);
        }
        __syncthreads();
    }

    const int colbase = n0 + wn + 2 * tg;
#pragma unroll
    for (int mi = 0; mi < 4; mi++) {
#pragma unroll
        for (int half = 0; half < 2; half++) {
            int row = wm + mi * 16 + gr + half * 8;
            int pr  = rows_sh[row];
            if (pr < 0) continue;
            float* yrow = g_ybuf + (size_t)pr * HIDDEN;
#pragma unroll
            for (int nj = 0; nj < 4; nj++) {
                float v0 = acc[mi][nj][half * 2 + 0];
                float v1 = acc[mi][nj][half * 2 + 1];
                *(float2*)&yrow[colbase + nj * 8] = make_float2(v0, v1);
            }
        }
    }
}

// ---------------- kernel 4: combine slots ----------------
__global__ __launch_bounds__(256) void combine_kernel(float* __restrict__ out)
{
    size_t idx = (size_t)blockIdx.x * blockDim.x + threadIdx.x;
    size_t total = (size_t)TOKENS * HIDDEN / 4;
    if (idx >= total) return;
    size_t t = idx / (HIDDEN / 4);
    size_t c = idx % (HIDDEN / 4);
    const float4* y0 = (const float4*)(g_ybuf + (size_t)(t * 2)     * HIDDEN) + c;
    const float4* y1 = (const float4*)(g_ybuf + (size_t)(t * 2 + 1) * HIDDEN) + c;
    float4 a = *y0, b = *y1;
    ((float4*)out)[idx] = make_float4(a.x + b.x, a.y + b.y, a.z + b.z, a.w + b.w);
}

// ---------------- launch ----------------
extern "C" void kernel_launch(void* const* d_in, const int* in_sizes, int n_in,
                              void* d_out, int out_size)
{
    const float* x  = (const float*)d_in[0];
    const float* wr = (const float*)d_in[1];
    const float* wg = (const float*)d_in[2];
    const float* wu = (const float*)d_in[3];
    const float* wd = (const float*)d_in[4];
    float* out = (float*)d_out;

    zero_counts_kernel<<<1, 32>>>();
    router_kernel<<<TOKENS, 256>>>(x, wr);

    dim3 g1(INTER / 64, TOKENS / 128, NEXP);    // 22 x 16 x 8
    gateup_kernel<<<g1, 256>>>(x, wg, wu);

    dim3 g2(HIDDEN / 128, TOKENS / 128, NEXP);  // 16 x 16 x 8
    down_kernel<<<g2, 256>>>(wd);

    size_t total4 = (size_t)TOKENS * HIDDEN / 4;
    combine_kernel<<<(unsigned)((total4 + 255) / 256), 256>>>(out);
}